// round 2
// baseline (speedup 1.0000x reference)
#include <cuda_runtime.h>
#include <cuda_bf16.h>

#define WS 7
#define DROP_PROB 0.1f
#define Hc 250          // H - WS + 1
#define Wc 250
#define Hdim 256
#define Wdim 256
#define MASK_ELEMS (Hdim * Wdim)        // 65536
#define MASK_VEC4  (MASK_ELEMS / 4)     // 16384 (power of two)
#define TOTAL_VEC4 (16u * 64u * MASK_VEC4)   // 16777216
#define HALF_VEC4  (TOTAL_VEC4 / 2u)         // 8388608 (multiple of MASK_VEC4)

// Scratch for the [256,256] broadcast mask (device global: no allocs allowed).
__device__ float g_mask[MASK_ELEMS];

// Kernel 1: mask[h][w] = 1 - max over anchors (a,b) in [h-6,h]x[w-6,w] ∩ [0,249]^2
// of (u[a][b] < DROP_PROB). 65536 threads, tiny; u is 250KB -> L2-resident.
__global__ void build_mask_kernel(const float* __restrict__ u) {
    int idx = blockIdx.x * blockDim.x + threadIdx.x;
    if (idx >= MASK_ELEMS) return;
    int h = idx >> 8;          // / 256
    int w = idx & 255;         // % 256

    int a0 = h - (WS - 1); if (a0 < 0) a0 = 0;
    int a1 = h;             if (a1 > Hc - 1) a1 = Hc - 1;
    int b0 = w - (WS - 1); if (b0 < 0) b0 = 0;
    int b1 = w;             if (b1 > Wc - 1) b1 = Wc - 1;

    int dropped = 0;
    for (int a = a0; a <= a1; ++a) {
        const float* row = u + a * Wc;
        for (int b = b0; b <= b1; ++b) {
            dropped |= (__ldg(row + b) < DROP_PROB);
        }
    }
    g_mask[idx] = dropped ? 0.0f : 1.0f;
}

// Kernel 2: streaming elementwise multiply with broadcast mask.
// Each thread handles two independent float4s, HALF_VEC4 apart, to raise MLP.
// HALF_VEC4 is a multiple of MASK_VEC4 (power-of-two period), so the mask
// index is (i & (MASK_VEC4-1)) for both halves.
__global__ void __launch_bounds__(256, 8)
apply_mask_kernel(const float4* __restrict__ x, float4* __restrict__ out) {
    unsigned int i = blockIdx.x * 256u + threadIdx.x;
    const float4* m4 = reinterpret_cast<const float4*>(g_mask);

    float4 x0 = x[i];
    float4 x1 = x[i + HALF_VEC4];
    float4 mv = __ldg(m4 + (i & (MASK_VEC4 - 1)));

    float4 o0, o1;
    o0.x = x0.x * mv.x; o0.y = x0.y * mv.y;
    o0.z = x0.z * mv.z; o0.w = x0.w * mv.w;
    o1.x = x1.x * mv.x; o1.y = x1.y * mv.y;
    o1.z = x1.z * mv.z; o1.w = x1.w * mv.w;

    out[i] = o0;
    out[i + HALF_VEC4] = o1;
}

extern "C" void kernel_launch(void* const* d_in, const int* in_sizes, int n_in,
                              void* d_out, int out_size) {
    const float* x = (const float*)d_in[0];   // [16,64,256,256] fp32
    const float* u = (const float*)d_in[1];   // [250,250] fp32
    float* out = (float*)d_out;

    // 1) build 256x256 mask
    build_mask_kernel<<<MASK_ELEMS / 256, 256>>>(u);

    // 2) apply: 16777216 float4 total, 2 per thread -> 8388608 threads
    apply_mask_kernel<<<HALF_VEC4 / 256, 256>>>(
        reinterpret_cast<const float4*>(x),
        reinterpret_cast<float4*>(out));
}

// round 6
// speedup vs baseline: 1.5075x; 1.5075x over previous
#include <cuda_runtime.h>
#include <cuda_bf16.h>

#define WS 7
#define DROP_PROB 0.1f
#define Hc 250          // H - WS + 1
#define Wc 250
#define Hdim 256
#define Wdim 256
#define MASK_ELEMS (Hdim * Wdim)        // 65536
#define MASK_VEC4  (MASK_ELEMS / 4)     // 16384 (power of two)
#define TOTAL_VEC4 (16u * 64u * MASK_VEC4)   // 16777216
#define HALF_VEC4  (TOTAL_VEC4 / 2u)         // 8388608 (multiple of MASK_VEC4)

// Scratch for the [256,256] broadcast mask (device global: no allocs allowed).
__device__ float g_mask[MASK_ELEMS];

// Kernel 1 (separable dilation): one block per output row h (256 blocks, 256 thr).
// Pass A (global->smem): colOR[w] = OR over a in [h-6,h]∩[0,Hc-1] of (u[a][w] < p)
// Pass B (smem->global): mask[h][w] = 1 - OR over b in [w-6,w]∩[0,Wc-1] of colOR[b]
__global__ void build_mask_kernel(const float* __restrict__ u) {
    __shared__ int colOR[Wdim];
    int h = blockIdx.x;
    int w = threadIdx.x;

    int v = 0;
    if (w < Wc) {
        int a0 = h - (WS - 1); if (a0 < 0) a0 = 0;
        int a1 = h;            if (a1 > Hc - 1) a1 = Hc - 1;
        #pragma unroll 7
        for (int a = a0; a <= a1; ++a)
            v |= (__ldg(u + a * Wc + w) < DROP_PROB);
    }
    colOR[w] = v;
    __syncthreads();

    int b0 = w - (WS - 1); if (b0 < 0) b0 = 0;
    int b1 = w;            if (b1 > Wc - 1) b1 = Wc - 1;
    int d = 0;
    #pragma unroll 7
    for (int b = b0; b <= b1; ++b)
        d |= colOR[b];

    g_mask[h * Wdim + w] = d ? 0.0f : 1.0f;
}

// Kernel 2: write-bound streaming apply. ~99.4% of mask positions are 0, so
// skip the x loads entirely for fully-dropped float4 groups and write zeros.
// Each thread covers two float4s HALF_VEC4 apart; they share the same (h,w)
// mask value because HALF_VEC4 is a multiple of the MASK_VEC4 period.
// Stores use cache-streaming (__stcs): write-once data, keep L2 for the mask.
__global__ void __launch_bounds__(256, 8)
apply_mask_kernel(const float4* __restrict__ x, float4* __restrict__ out) {
    unsigned int i = blockIdx.x * 256u + threadIdx.x;
    const float4* m4 = reinterpret_cast<const float4*>(g_mask);
    float4 mv = __ldg(m4 + (i & (MASK_VEC4 - 1)));

    float4 o0 = make_float4(0.f, 0.f, 0.f, 0.f);
    float4 o1 = make_float4(0.f, 0.f, 0.f, 0.f);

    if ((mv.x + mv.y + mv.z + mv.w) != 0.0f) {
        float4 x0 = x[i];
        float4 x1 = x[i + HALF_VEC4];
        o0.x = x0.x * mv.x; o0.y = x0.y * mv.y;
        o0.z = x0.z * mv.z; o0.w = x0.w * mv.w;
        o1.x = x1.x * mv.x; o1.y = x1.y * mv.y;
        o1.z = x1.z * mv.z; o1.w = x1.w * mv.w;
    }

    __stcs(out + i, o0);
    __stcs(out + i + HALF_VEC4, o1);
}

extern "C" void kernel_launch(void* const* d_in, const int* in_sizes, int n_in,
                              void* d_out, int out_size) {
    const float* x = (const float*)d_in[0];   // [16,64,256,256] fp32
    const float* u = (const float*)d_in[1];   // [250,250] fp32
    float* out = (float*)d_out;

    // 1) build 256x256 mask (separable 7x7 max-dilation)
    build_mask_kernel<<<Hdim, Wdim>>>(u);

    // 2) apply: 16777216 float4 total, 2 per thread -> 8388608 threads
    apply_mask_kernel<<<HALF_VEC4 / 256, 256>>>(
        reinterpret_cast<const float4*>(x),
        reinterpret_cast<float4*>(out));
}